// round 14
// baseline (speedup 1.0000x reference)
#include <cuda_runtime.h>
#include <cuda_fp16.h>
#include <math.h>
#include <stdint.h>

// Problem constants
#define BB    4
#define NSEQ  2048
#define DIM   1024
#define NH    16
#define HD    64
#define MTOK  (BB*NSEQ)      // 8192 tokens
#define BHN   (BB*NH)        // 64 batch*heads

// ---------------------------------------------------------------------------
// Static device scratch
// ---------------------------------------------------------------------------
__device__ __half g_xr    [(size_t)MTOK * DIM];
__device__ __half g_qkv   [(size_t)MTOK * 3 * DIM];
__device__ __half g_q     [(size_t)BHN * NSEQ * HD];
__device__ __half g_k     [(size_t)BHN * NSEQ * HD];
__device__ __half g_v     [(size_t)BHN * NSEQ * HD];
__device__ __half g_msgin [(size_t)MTOK * DIM];
__device__ __half g_h     [(size_t)MTOK * 2 * DIM];
__device__ float  g_hf32  [(size_t)MTOK * 2 * DIM];  // FFN0a partial (fp32)
// weights
__device__ __half g_wqkvT [(size_t)(3*DIM) * DIM];   // [N][K]
__device__ __half g_woutNT[(size_t)DIM * DIM];       // out_w row-major [d][e]
__device__ __half g_w0T   [(size_t)(2*DIM) * (2*DIM)];  // [N][2048]: k<1024 W0_top, k>=1024 Wf
__device__ __half g_wf    [(size_t)(2*DIM) * DIM];   // Wf^T scratch [n][d]
__device__ __half g_w3T   [(size_t)DIM * (2*DIM)];
__device__ float  g_b0f   [2*DIM];                   // fused FFN0 bias

// ---------------------------------------------------------------------------
// helpers
// ---------------------------------------------------------------------------
__device__ __forceinline__ void mma16(float c[4], const unsigned a[4],
                                      unsigned b0, unsigned b1)
{
    asm volatile(
        "mma.sync.aligned.m16n8k16.row.col.f32.f16.f16.f32 "
        "{%0,%1,%2,%3}, {%4,%5,%6,%7}, {%8,%9}, {%0,%1,%2,%3};"
        : "+f"(c[0]), "+f"(c[1]), "+f"(c[2]), "+f"(c[3])
        : "r"(a[0]), "r"(a[1]), "r"(a[2]), "r"(a[3]), "r"(b0), "r"(b1));
}

__device__ __forceinline__ void ldsm4(unsigned &r0, unsigned &r1,
                                      unsigned &r2, unsigned &r3, const void* p)
{
    unsigned a = (unsigned)__cvta_generic_to_shared(p);
    asm volatile("ldmatrix.sync.aligned.m8n8.x4.shared.b16 {%0,%1,%2,%3}, [%4];"
                 : "=r"(r0), "=r"(r1), "=r"(r2), "=r"(r3) : "r"(a));
}

__device__ __forceinline__ void ldsm4t(unsigned &r0, unsigned &r1,
                                       unsigned &r2, unsigned &r3, const void* p)
{
    unsigned a = (unsigned)__cvta_generic_to_shared(p);
    asm volatile("ldmatrix.sync.aligned.m8n8.x4.trans.shared.b16 {%0,%1,%2,%3}, [%4];"
                 : "=r"(r0), "=r"(r1), "=r"(r2), "=r"(r3) : "r"(a));
}

__device__ __forceinline__ void cp16(void* s, const void* g)
{
    unsigned a = (unsigned)__cvta_generic_to_shared(s);
    asm volatile("cp.async.cg.shared.global [%0], [%1], 16;" :: "r"(a), "l"(g));
}
#define CP_COMMIT() asm volatile("cp.async.commit_group;")
#define CP_WAIT(n)  asm volatile("cp.async.wait_group %0;" :: "n"(n))

__device__ __forceinline__ unsigned h2bits(float a, float b)
{
    __half2 h = __floats2half2_rn(a, b);
    return *reinterpret_cast<unsigned*>(&h);
}

// ---------------------------------------------------------------------------
// fp16 GEMM: C[M,N] = [A | A2][M,K] * BT[N,K(ldb)]^T (+bias) (+resid fp32)
// BM=BN=128, BK=64 halves, 3-stage cp.async, ldmatrix x4 frags, 2 CTAs/SM.
// OUT_HALF=1: C half (resid added pre-round if non-null).
// OUT_HALF=0: C float (resid added if non-null).
// ---------------------------------------------------------------------------
#define GS_LDH   72
#define GS_STAGE (2 * 128 * GS_LDH)          // halves per stage
#define GEMM_SMEM (3 * GS_STAGE * 2)         // bytes

template<int OUT_HALF>
__global__ __launch_bounds__(256, 2) void hgemm(
    const __half* __restrict__ A, const __half* __restrict__ A2,
    const __half* __restrict__ BT,
    const float* __restrict__ bias, const float* __restrict__ resid,
    void* __restrict__ Cv,
    int K, int K1, int lda, int lda2, int ldb, int ldc)
{
    extern __shared__ __half hs[];
    const int tid  = threadIdx.x;
    const int lane = tid & 31, warp = tid >> 5;
    const int g    = lane >> 2, tg = lane & 3;
    const int wm   = warp & 1, wn = warp >> 1;       // 2x4 warps, 64x32 tiles
    const int row0 = blockIdx.y * 128, col0 = blockIdx.x * 128;

    const int lrow = (lane & 7) + ((lane >> 3) & 1) * 8;   // A ldsm row
    const int lcol = ((lane >> 4) & 1) * 8;                // A ldsm col (halves)
    const int brow = (lane & 7) + ((lane >> 4) & 1) * 8;   // B ldsm row
    const int bcol = ((lane >> 3) & 1) * 8;                // B ldsm col

    float acc[4][4][4] = {};

    auto issue = [&](int kt) {
        int k0 = kt * 64;
        if (k0 < K) {
            __half* sa = hs + (kt % 3) * GS_STAGE;
            __half* sb = sa + 128 * GS_LDH;
            const __half* Asrc = A; int kk = k0, ld = lda;
            if (A2 && k0 >= K1) { Asrc = A2; kk = k0 - K1; ld = lda2; }
            #pragma unroll
            for (int i = 0; i < 4; i++) {
                int id = tid + i * 256;
                int r = id >> 3, c = (id & 7) * 8;
                cp16(sa + r * GS_LDH + c, Asrc + (size_t)(row0 + r) * ld + kk + c);
                cp16(sb + r * GS_LDH + c, BT + (size_t)(col0 + r) * ldb + k0 + c);
            }
        }
        CP_COMMIT();
    };

    auto compute = [&](int kt) {
        const __half* sa = hs + (kt % 3) * GS_STAGE;
        const __half* sb = sa + 128 * GS_LDH;
        #pragma unroll
        for (int ks = 0; ks < 4; ks++) {
            unsigned af[4][4], bf[4][2];
            #pragma unroll
            for (int mi = 0; mi < 4; mi++)
                ldsm4(af[mi][0], af[mi][1], af[mi][2], af[mi][3],
                      sa + (wm * 64 + mi * 16 + lrow) * GS_LDH + ks * 16 + lcol);
            #pragma unroll
            for (int p = 0; p < 2; p++) {
                unsigned r0, r1, r2, r3;
                ldsm4(r0, r1, r2, r3,
                      sb + (wn * 32 + p * 16 + brow) * GS_LDH + ks * 16 + bcol);
                bf[2*p][0] = r0; bf[2*p][1] = r1;
                bf[2*p+1][0] = r2; bf[2*p+1][1] = r3;
            }
            #pragma unroll
            for (int mi = 0; mi < 4; mi++)
                #pragma unroll
                for (int ni = 0; ni < 4; ni++)
                    mma16(acc[mi][ni], af[mi], bf[ni][0], bf[ni][1]);
        }
    };

    issue(0); issue(1);
    const int KT = K / 64;
    CP_WAIT(1); __syncthreads();
    for (int kt = 0; kt < KT; kt++) {
        issue(kt + 2);
        compute(kt);
        CP_WAIT(1); __syncthreads();
    }

    #pragma unroll
    for (int mi = 0; mi < 4; mi++) {
        int rb = row0 + wm * 64 + mi * 16 + g;
        #pragma unroll
        for (int ni = 0; ni < 4; ni++) {
            int cb = col0 + wn * 32 + ni * 8 + 2 * tg;
            float b0v = bias ? bias[cb]     : 0.f;
            float b1v = bias ? bias[cb + 1] : 0.f;
            float v00 = acc[mi][ni][0] + b0v, v01 = acc[mi][ni][1] + b1v;
            float v10 = acc[mi][ni][2] + b0v, v11 = acc[mi][ni][3] + b1v;
            if (resid) {
                float2 ra = *(const float2*)(resid + (size_t)rb * ldc + cb);
                float2 rbv = *(const float2*)(resid + (size_t)(rb + 8) * ldc + cb);
                v00 += ra.x; v01 += ra.y; v10 += rbv.x; v11 += rbv.y;
            }
            if (OUT_HALF) {
                __half* C = (__half*)Cv;
                *(__half2*)(C + (size_t)rb * ldc + cb) = __floats2half2_rn(v00, v01);
                *(__half2*)(C + (size_t)(rb + 8) * ldc + cb) = __floats2half2_rn(v10, v11);
            } else {
                float* C = (float*)Cv;
                *(float2*)(C + (size_t)rb * ldc + cb)       = make_float2(v00, v01);
                *(float2*)(C + (size_t)(rb + 8) * ldc + cb) = make_float2(v10, v11);
            }
        }
    }
}

// ---------------------------------------------------------------------------
// Weight prep
// ---------------------------------------------------------------------------
__global__ void wt_round_T(const float* __restrict__ in, __half* __restrict__ out,
                           int K, int N)
{
    __shared__ float t[32][33];
    int n0 = blockIdx.x * 32, k0 = blockIdx.y * 32;
    int tx = threadIdx.x, ty = threadIdx.y;
    #pragma unroll
    for (int i = 0; i < 32; i += 8)
        t[ty + i][tx] = in[(size_t)(k0 + ty + i) * N + n0 + tx];
    __syncthreads();
    #pragma unroll
    for (int i = 0; i < 32; i += 8)
        out[(size_t)(n0 + ty + i) * K + k0 + tx] = __float2half_rn(t[tx][ty + i]);
}

__global__ void round_copy(const float* __restrict__ src, __half* __restrict__ dst,
                           size_t n2)
{
    size_t idx = (size_t)blockIdx.x * blockDim.x + threadIdx.x;
    if (idx >= n2) return;
    float2 v = *(const float2*)(src + idx * 2);
    *(__half2*)(dst + idx * 2) = __floats2half2_rn(v.x, v.y);
}

// copy Wf^T scratch [2048][1024] into w0T[:, 1024:2048]
__global__ void copy_wf()
{
    size_t idx = (size_t)blockIdx.x * blockDim.x + threadIdx.x;   // half2 units
    if (idx >= (size_t)(2 * DIM) * DIM / 2) return;
    size_t n = idx / (DIM / 2);
    size_t d2 = idx % (DIM / 2);
    *(__half2*)(g_w0T + n * (2 * DIM) + DIM + d2 * 2) =
        *(__half2*)(g_wf + n * DIM + d2 * 2);
}

// fused bias: b0f[n] = ffn0_b[n] + sum_e out_b[e] * ffn0_w[(1024+e)*2048 + n]
__global__ void bias_fuse(const float* __restrict__ ffn0_b,
                          const float* __restrict__ out_b,
                          const float* __restrict__ ffn0_w)
{
    int n = blockIdx.x * 256 + threadIdx.x;
    float acc = ffn0_b[n];
    for (int e = 0; e < DIM; e++)
        acc = fmaf(out_b[e], ffn0_w[(size_t)(DIM + e) * (2 * DIM) + n], acc);
    g_b0f[n] = acc;
}

// ---------------------------------------------------------------------------
// Flash attention, fp16 mma m16n8k16, HD=64, cp.async double-buffered K/V.
// P in registers; S/PV in two 64-col KV chunks; 2 CTAs/SM; base-2 softmax.
// ---------------------------------------------------------------------------
#define FL_KV_OFF   9216
#define FL_SMEM_BYTES (46080 * 2)
#define SC_LOG2E 0.18033688011112042f   // 0.125 * log2(e)

__global__ __launch_bounds__(256, 2) void flash_kernel(
    const __half* __restrict__ Q, const __half* __restrict__ K,
    const __half* __restrict__ V, __half* __restrict__ O)
{
    extern __shared__ __half sm[];

    const int tid  = threadIdx.x;
    const int w    = tid >> 5, lane = tid & 31;
    const int g    = lane >> 2, tg = lane & 3;
    const int bh   = blockIdx.y;
    const int q0   = blockIdx.x * 128;
    const int b    = bh >> 4, h = bh & 15;

    const int lrow = (lane & 7) + ((lane >> 3) & 1) * 8;
    const int lcol = ((lane >> 4) & 1) * 8;
    const int brow = (lane & 7) + ((lane >> 4) & 1) * 8;
    const int bcol = ((lane >> 3) & 1) * 8;

    const __half* Qp = Q + (size_t)bh * NSEQ * HD;
    const __half* Kp = K + (size_t)bh * NSEQ * HD;
    const __half* Vp = V + (size_t)bh * NSEQ * HD;

    auto issue = [&](int j) {
        __half* Kb = sm + FL_KV_OFF + (j & 1) * 18432;
        __half* Vb = Kb + 9216;
        #pragma unroll
        for (int i = 0; i < 4; i++) {
            int id = tid + i * 256;
            int r = id >> 3, c = (id & 7) * 8;
            size_t go = (size_t)(j * 128 + r) * HD + c;
            cp16(Kb + r * 72 + c, Kp + go);
            cp16(Vb + r * 72 + c, Vp + go);
        }
        CP_COMMIT();
    };

    issue(0);

    #pragma unroll
    for (int i = 0; i < 4; i++) {
        int id = tid + i * 256;
        int r = id >> 3, c = (id & 7) * 8;
        *(uint4*)(sm + r * 72 + c) = *(const uint4*)(Qp + (size_t)(q0 + r) * HD + c);
    }
    __syncthreads();
    unsigned qf[4][4];
    #pragma unroll
    for (int ks = 0; ks < 4; ks++)
        ldsm4(qf[ks][0], qf[ks][1], qf[ks][2], qf[ks][3],
              sm + (w * 16 + lrow) * 72 + ks * 16 + lcol);

    float m0 = -1e30f, m1 = -1e30f, l0 = 0.f, l1 = 0.f;
    float oa[8][4] = {};

    for (int j = 0; j < 16; j++) {
        if (j < 15) { issue(j + 1); CP_WAIT(1); }
        else        { CP_WAIT(0); }
        __syncthreads();

        const __half* Ks = sm + FL_KV_OFF + (j & 1) * 18432;
        const __half* Vs = Ks + 9216;

        #pragma unroll
        for (int half = 0; half < 2; half++) {
            float s[8][4];
            #pragma unroll
            for (int ni = 0; ni < 8; ni++)
                s[ni][0] = s[ni][1] = s[ni][2] = s[ni][3] = 0.f;
            #pragma unroll
            for (int ks = 0; ks < 4; ks++) {
                #pragma unroll
                for (int n2 = 0; n2 < 4; n2++) {
                    unsigned r0, r1, r2, r3;
                    ldsm4(r0, r1, r2, r3,
                          Ks + (half * 64 + n2 * 16 + brow) * 72 + ks * 16 + bcol);
                    mma16(s[2*n2],     qf[ks], r0, r1);
                    mma16(s[2*n2 + 1], qf[ks], r2, r3);
                }
            }

            float mt0 = -1e30f, mt1 = -1e30f;
            #pragma unroll
            for (int ni = 0; ni < 8; ni++) {
                s[ni][0] *= SC_LOG2E; s[ni][1] *= SC_LOG2E;
                s[ni][2] *= SC_LOG2E; s[ni][3] *= SC_LOG2E;
                mt0 = fmaxf(mt0, fmaxf(s[ni][0], s[ni][1]));
                mt1 = fmaxf(mt1, fmaxf(s[ni][2], s[ni][3]));
            }
            mt0 = fmaxf(mt0, __shfl_xor_sync(~0u, mt0, 1));
            mt0 = fmaxf(mt0, __shfl_xor_sync(~0u, mt0, 2));
            mt1 = fmaxf(mt1, __shfl_xor_sync(~0u, mt1, 1));
            mt1 = fmaxf(mt1, __shfl_xor_sync(~0u, mt1, 2));
            float m0n = fmaxf(m0, mt0), m1n = fmaxf(m1, mt1);
            bool changed = (m0n > m0) || (m1n > m1);
            float rs0 = 0.f, rs1 = 0.f;
            #pragma unroll
            for (int ni = 0; ni < 8; ni++) {
                s[ni][0] = exp2f(s[ni][0] - m0n);
                s[ni][1] = exp2f(s[ni][1] - m0n);
                s[ni][2] = exp2f(s[ni][2] - m1n);
                s[ni][3] = exp2f(s[ni][3] - m1n);
                rs0 += s[ni][0] + s[ni][1];
                rs1 += s[ni][2] + s[ni][3];
            }
            rs0 += __shfl_xor_sync(~0u, rs0, 1); rs0 += __shfl_xor_sync(~0u, rs0, 2);
            rs1 += __shfl_xor_sync(~0u, rs1, 1); rs1 += __shfl_xor_sync(~0u, rs1, 2);
            if (__any_sync(~0u, changed)) {
                float c0 = exp2f(m0 - m0n), c1 = exp2f(m1 - m1n);
                l0 = l0 * c0 + rs0; l1 = l1 * c1 + rs1;
                #pragma unroll
                for (int ni = 0; ni < 8; ni++) {
                    oa[ni][0] *= c0; oa[ni][1] *= c0;
                    oa[ni][2] *= c1; oa[ni][3] *= c1;
                }
                m0 = m0n; m1 = m1n;
            } else {
                l0 += rs0; l1 += rs1;
            }

            #pragma unroll
            for (int c = 0; c < 4; c++) {
                unsigned a[4];
                a[0] = h2bits(s[2*c][0],     s[2*c][1]);
                a[1] = h2bits(s[2*c][2],     s[2*c][3]);
                a[2] = h2bits(s[2*c + 1][0], s[2*c + 1][1]);
                a[3] = h2bits(s[2*c + 1][2], s[2*c + 1][3]);
                #pragma unroll
                for (int n2 = 0; n2 < 4; n2++) {
                    unsigned r0, r1, r2, r3;
                    ldsm4t(r0, r1, r2, r3,
                           Vs + (half * 64 + c * 16 + lrow) * 72 + n2 * 16 + lcol);
                    mma16(oa[2*n2],     a, r0, r1);
                    mma16(oa[2*n2 + 1], a, r2, r3);
                }
            }
        }
        __syncthreads();
    }

    float i0 = 1.f / l0, i1 = 1.f / l1;
    int r0 = q0 + w * 16 + g, r1 = r0 + 8;
    __half* Op = O + ((size_t)b * NSEQ) * DIM + h * HD;
    #pragma unroll
    for (int ni = 0; ni < 8; ni++) {
        int cb = ni * 8 + 2 * tg;
        *(__half2*)(Op + (size_t)r0 * DIM + cb) =
            __floats2half2_rn(oa[ni][0] * i0, oa[ni][1] * i0);
        *(__half2*)(Op + (size_t)r1 * DIM + cb) =
            __floats2half2_rn(oa[ni][2] * i1, oa[ni][3] * i1);
    }
}

// ---------------------------------------------------------------------------
// RoPE + QKV split (half in, half out)
// ---------------------------------------------------------------------------
__global__ void rope_split_kernel(const __half* __restrict__ qkv,
                                  const float* __restrict__ enc)
{
    size_t idx = (size_t)blockIdx.x * blockDim.x + threadIdx.x;
    const size_t total = (size_t)BB * NH * NSEQ * (HD / 2);
    if (idx >= total) return;
    int pair = idx & 31;
    size_t t = idx >> 5;
    int n = t & (NSEQ - 1); t >>= 11;
    int h = t & (NH - 1);
    int b = (int)(t >> 4);

    const __half* src = qkv + ((size_t)(b * NSEQ + n) * (3 * DIM)
                               + h * (HD * 3) + pair * 6);
    float q0 = __half2float(src[0]), k0 = __half2float(src[1]);
    float v0 = __half2float(src[2]), q1 = __half2float(src[3]);
    float k1 = __half2float(src[4]), v1 = __half2float(src[5]);

    const float* e0 = enc + (size_t)n * HD + pair * 2;
    const float* e1 = enc + (size_t)NSEQ * HD + (size_t)n * HD + pair * 2;
    float f00 = e0[0], f01 = e0[1], f10 = e1[0], f11 = e1[1];

    size_t o = ((size_t)(b * NH + h) * NSEQ + n) * HD + pair * 2;
    *(__half2*)(g_q + o) = __floats2half2_rn(q0 * f00 - q1 * f10,
                                             q1 * f01 + q0 * f11);
    *(__half2*)(g_k + o) = __floats2half2_rn(k0 * f00 - k1 * f10,
                                             k1 * f01 + k0 * f11);
    *(__half2*)(g_v + o) = __floats2half2_rn(v0, v1);
}

// LayerNorm (2048) + exact GELU, in place on g_h (half).
__global__ __launch_bounds__(256) void ln_gelu_kernel(const float* __restrict__ scale,
                                                      const float* __restrict__ bias)
{
    const int n = 2 * DIM;
    __half* p = g_h + (size_t)blockIdx.x * n;
    const int tid = threadIdx.x;
    __shared__ float s8a[8], s8b[8];

    float s = 0.f, sq = 0.f;
    for (int i = tid; i < n / 2; i += 256) {
        float2 v = __half22float2(*(__half2*)(p + i * 2));
        s += v.x + v.y;
        sq = fmaf(v.x, v.x, fmaf(v.y, v.y, sq));
    }
    #pragma unroll
    for (int o = 16; o > 0; o >>= 1) {
        s  += __shfl_xor_sync(~0u, s, o);
        sq += __shfl_xor_sync(~0u, sq, o);
    }
    if ((tid & 31) == 0) { s8a[tid >> 5] = s; s8b[tid >> 5] = sq; }
    __syncthreads();
    s = 0.f; sq = 0.f;
    #pragma unroll
    for (int i = 0; i < 8; i++) { s += s8a[i]; sq += s8b[i]; }
    float mu = s / n;
    float var = sq / n - mu * mu;
    float rstd = rsqrtf(var + 1e-5f);

    for (int i = tid; i < n / 2; i += 256) {
        float2 v = __half22float2(*(__half2*)(p + i * 2));
        float a = (v.x - mu) * rstd * scale[i * 2]     + bias[i * 2];
        float c = (v.y - mu) * rstd * scale[i * 2 + 1] + bias[i * 2 + 1];
        a = 0.5f * a * (1.f + erff(a * 0.70710678118654752f));
        c = 0.5f * c * (1.f + erff(c * 0.70710678118654752f));
        *(__half2*)(p + i * 2) = __floats2half2_rn(a, c);
    }
}

// ---------------------------------------------------------------------------
// Host
// ---------------------------------------------------------------------------
static inline void* sym(const void* s)
{
    void* p = nullptr;
    cudaGetSymbolAddress(&p, s);
    return p;
}

extern "C" void kernel_launch(void* const* d_in, const int* in_sizes, int n_in,
                              void* d_out, int out_size)
{
    const float* x       = (const float*)d_in[0];
    const float* enc     = (const float*)d_in[1];
    const float* Wqkv_w  = (const float*)d_in[2];
    const float* Wqkv_b  = (const float*)d_in[3];
    const float* out_w   = (const float*)d_in[4];
    const float* out_b   = (const float*)d_in[5];
    const float* ffn0_w  = (const float*)d_in[6];
    const float* ffn0_b  = (const float*)d_in[7];
    const float* ln_s    = (const float*)d_in[8];
    const float* ln_b    = (const float*)d_in[9];
    const float* ffn3_w  = (const float*)d_in[10];
    const float* ffn3_b  = (const float*)d_in[11];
    float* out = (float*)d_out;

    __half* xr     = (__half*)sym(g_xr);
    __half* qkv    = (__half*)sym(g_qkv);
    __half* q      = (__half*)sym(g_q);
    __half* k      = (__half*)sym(g_k);
    __half* v      = (__half*)sym(g_v);
    __half* msgin  = (__half*)sym(g_msgin);
    __half* hbuf   = (__half*)sym(g_h);
    float*  hf32   = (float*)sym(g_hf32);
    __half* wqkvT  = (__half*)sym(g_wqkvT);
    __half* woutNT = (__half*)sym(g_woutNT);
    __half* w0T    = (__half*)sym(g_w0T);
    __half* wf     = (__half*)sym(g_wf);
    __half* w3T    = (__half*)sym(g_w3T);
    float*  b0f    = (float*)sym(g_b0f);

    static cudaStream_t s2 = nullptr;
    static cudaEvent_t evFork = nullptr, evFork2 = nullptr, evJoin = nullptr;
    static bool attr_done = false;
    if (!attr_done) {
        cudaFuncSetAttribute(flash_kernel,
            cudaFuncAttributeMaxDynamicSharedMemorySize, FL_SMEM_BYTES);
        cudaFuncSetAttribute(hgemm<0>,
            cudaFuncAttributeMaxDynamicSharedMemorySize, GEMM_SMEM);
        cudaFuncSetAttribute(hgemm<1>,
            cudaFuncAttributeMaxDynamicSharedMemorySize, GEMM_SMEM);
        cudaStreamCreateWithFlags(&s2, cudaStreamNonBlocking);
        cudaEventCreateWithFlags(&evFork, cudaEventDisableTiming);
        cudaEventCreateWithFlags(&evFork2, cudaEventDisableTiming);
        cudaEventCreateWithFlags(&evJoin, cudaEventDisableTiming);
        attr_done = true;
    }

    // ---- fork: FFN-weight prep on side stream ----
    cudaEventRecord(evFork, 0);
    cudaStreamWaitEvent(s2, evFork, 0);

    wt_round_T<<<dim3(2 * DIM / 32, 2 * DIM / 32), dim3(32, 8), 0, s2>>>(
        ffn0_w, w0T, 2 * DIM, 2 * DIM);
    wt_round_T<<<dim3(DIM / 32, 2 * DIM / 32), dim3(32, 8), 0, s2>>>(
        ffn3_w, w3T, 2 * DIM, DIM);
    round_copy<<<(DIM * DIM / 2 + 255) / 256, 256, 0, s2>>>(
        out_w, woutNT, (size_t)DIM * DIM / 2);
    hgemm<1><<<dim3(DIM / 128, 2 * DIM / 128), 256, GEMM_SMEM, s2>>>(
        w0T + DIM, nullptr, woutNT, nullptr, nullptr, wf,
        DIM, DIM, 2 * DIM, 0, DIM, DIM);
    copy_wf<<<((size_t)(2 * DIM) * DIM / 2 + 255) / 256, 256, 0, s2>>>();
    bias_fuse<<<2 * DIM / 256, 256, 0, s2>>>(ffn0_b, out_b, ffn0_w);

    // ---- main stream: QKV chain ----
    wt_round_T<<<dim3(3 * DIM / 32, DIM / 32), dim3(32, 8)>>>(Wqkv_w, wqkvT, DIM, 3 * DIM);
    round_copy<<<((size_t)MTOK * DIM / 2 + 255) / 256, 256>>>(x, xr, (size_t)MTOK * DIM / 2);
    cudaEventRecord(evFork2, 0);   // xr ready

    hgemm<1><<<dim3(3 * DIM / 128, MTOK / 128), 256, GEMM_SMEM>>>(
        xr, nullptr, wqkvT, Wqkv_b, nullptr, qkv, DIM, DIM, DIM, 0, DIM, 3 * DIM);

    // ---- side stream: FFN0a = xr * W0_top -> hf32 (overlaps flash) ----
    cudaStreamWaitEvent(s2, evFork2, 0);
    hgemm<0><<<dim3(2 * DIM / 128, MTOK / 128), 256, GEMM_SMEM, s2>>>(
        xr, nullptr, w0T, nullptr, nullptr, hf32,
        DIM, DIM, DIM, 0, 2 * DIM, 2 * DIM);
    cudaEventRecord(evJoin, s2);

    {
        size_t total = (size_t)BB * NH * NSEQ * (HD / 2);
        rope_split_kernel<<<(unsigned)((total + 255) / 256), 256>>>(qkv, enc);
    }

    flash_kernel<<<dim3(NSEQ / 128, BHN), 256, FL_SMEM_BYTES>>>(
        q, k, v, msgin);

    // ---- join: FFN0b = msgin * Wf + b0f + hf32 -> hbuf ----
    cudaStreamWaitEvent(0, evJoin, 0);
    hgemm<1><<<dim3(2 * DIM / 128, MTOK / 128), 256, GEMM_SMEM>>>(
        msgin, nullptr, w0T + DIM, b0f, hf32, hbuf,
        DIM, DIM, DIM, 0, 2 * DIM, 2 * DIM);

    ln_gelu_kernel<<<MTOK, 256>>>(ln_s, ln_b);

    hgemm<0><<<dim3(DIM / 128, MTOK / 128), 256, GEMM_SMEM>>>(
        hbuf, nullptr, w3T, ffn3_b, x, out, 2 * DIM, 2 * DIM, 2 * DIM, 0, 2 * DIM, DIM);
}

// round 15
// speedup vs baseline: 1.0548x; 1.0548x over previous
#include <cuda_runtime.h>
#include <cuda_fp16.h>
#include <math.h>
#include <stdint.h>

// Problem constants
#define BB    4
#define NSEQ  2048
#define DIM   1024
#define NH    16
#define HD    64
#define MTOK  (BB*NSEQ)      // 8192 tokens
#define BHN   (BB*NH)        // 64 batch*heads

// ---------------------------------------------------------------------------
// Static device scratch
// ---------------------------------------------------------------------------
__device__ __half g_xr    [(size_t)MTOK * DIM];
__device__ __half g_qkv   [(size_t)MTOK * 3 * DIM];  // [tok][ q | k | v ], each [h][d]
__device__ __half g_msgin [(size_t)MTOK * DIM];
__device__ __half g_h     [(size_t)MTOK * 2 * DIM];
// weights
__device__ __half g_wqkvT [(size_t)(3*DIM) * DIM];   // permuted rows [n'][K]
__device__ float  g_bqkv  [3*DIM];                   // permuted QKV bias
__device__ __half g_woutNT[(size_t)DIM * DIM];       // out_w row-major [d][e]
__device__ __half g_w0T   [(size_t)(2*DIM) * (2*DIM)];  // [N][2048]: k<1024 W0_top, k>=1024 Wf
__device__ __half g_wf    [(size_t)(2*DIM) * DIM];   // Wf^T scratch [n][d]
__device__ __half g_w3T   [(size_t)DIM * (2*DIM)];
__device__ float  g_b0f   [2*DIM];                   // fused FFN0 bias

// ---------------------------------------------------------------------------
// helpers
// ---------------------------------------------------------------------------
__device__ __forceinline__ void mma16(float c[4], const unsigned a[4],
                                      unsigned b0, unsigned b1)
{
    asm volatile(
        "mma.sync.aligned.m16n8k16.row.col.f32.f16.f16.f32 "
        "{%0,%1,%2,%3}, {%4,%5,%6,%7}, {%8,%9}, {%0,%1,%2,%3};"
        : "+f"(c[0]), "+f"(c[1]), "+f"(c[2]), "+f"(c[3])
        : "r"(a[0]), "r"(a[1]), "r"(a[2]), "r"(a[3]), "r"(b0), "r"(b1));
}

__device__ __forceinline__ void ldsm4(unsigned &r0, unsigned &r1,
                                      unsigned &r2, unsigned &r3, const void* p)
{
    unsigned a = (unsigned)__cvta_generic_to_shared(p);
    asm volatile("ldmatrix.sync.aligned.m8n8.x4.shared.b16 {%0,%1,%2,%3}, [%4];"
                 : "=r"(r0), "=r"(r1), "=r"(r2), "=r"(r3) : "r"(a));
}

__device__ __forceinline__ void ldsm4t(unsigned &r0, unsigned &r1,
                                       unsigned &r2, unsigned &r3, const void* p)
{
    unsigned a = (unsigned)__cvta_generic_to_shared(p);
    asm volatile("ldmatrix.sync.aligned.m8n8.x4.trans.shared.b16 {%0,%1,%2,%3}, [%4];"
                 : "=r"(r0), "=r"(r1), "=r"(r2), "=r"(r3) : "r"(a));
}

__device__ __forceinline__ void cp16(void* s, const void* g)
{
    unsigned a = (unsigned)__cvta_generic_to_shared(s);
    asm volatile("cp.async.cg.shared.global [%0], [%1], 16;" :: "r"(a), "l"(g));
}
#define CP_COMMIT() asm volatile("cp.async.commit_group;")
#define CP_WAIT(n)  asm volatile("cp.async.wait_group %0;" :: "n"(n))

__device__ __forceinline__ unsigned h2bits(float a, float b)
{
    __half2 h = __floats2half2_rn(a, b);
    return *reinterpret_cast<unsigned*>(&h);
}

// ---------------------------------------------------------------------------
// fp16 GEMM: C[M,N] = [A | A2][M,K] * BT[N,K]^T (+bias) (+resid)
// BM=BN=128, BK=64 halves, 3-stage cp.async, ldmatrix x4 frags, 2 CTAs/SM.
// ---------------------------------------------------------------------------
#define GS_LDH   72
#define GS_STAGE (2 * 128 * GS_LDH)          // halves per stage
#define GEMM_SMEM (3 * GS_STAGE * 2)         // bytes

template<int OUT_HALF>
__global__ __launch_bounds__(256, 2) void hgemm(
    const __half* __restrict__ A, const __half* __restrict__ A2,
    const __half* __restrict__ BT,
    const float* __restrict__ bias, const float* __restrict__ resid,
    void* __restrict__ Cv,
    int K, int K1, int lda, int lda2, int ldc)
{
    extern __shared__ __half hs[];
    const int tid  = threadIdx.x;
    const int lane = tid & 31, warp = tid >> 5;
    const int g    = lane >> 2, tg = lane & 3;
    const int wm   = warp & 1, wn = warp >> 1;       // 2x4 warps, 64x32 tiles
    const int row0 = blockIdx.y * 128, col0 = blockIdx.x * 128;

    const int lrow = (lane & 7) + ((lane >> 3) & 1) * 8;   // A ldsm row
    const int lcol = ((lane >> 4) & 1) * 8;                // A ldsm col (halves)
    const int brow = (lane & 7) + ((lane >> 4) & 1) * 8;   // B ldsm row
    const int bcol = ((lane >> 3) & 1) * 8;                // B ldsm col

    float acc[4][4][4] = {};

    auto issue = [&](int kt) {
        int k0 = kt * 64;
        if (k0 < K) {
            __half* sa = hs + (kt % 3) * GS_STAGE;
            __half* sb = sa + 128 * GS_LDH;
            const __half* Asrc = A; int kk = k0, ld = lda;
            if (A2 && k0 >= K1) { Asrc = A2; kk = k0 - K1; ld = lda2; }
            #pragma unroll
            for (int i = 0; i < 4; i++) {
                int id = tid + i * 256;
                int r = id >> 3, c = (id & 7) * 8;
                cp16(sa + r * GS_LDH + c, Asrc + (size_t)(row0 + r) * ld + kk + c);
                cp16(sb + r * GS_LDH + c, BT + (size_t)(col0 + r) * K + k0 + c);
            }
        }
        CP_COMMIT();
    };

    auto compute = [&](int kt) {
        const __half* sa = hs + (kt % 3) * GS_STAGE;
        const __half* sb = sa + 128 * GS_LDH;
        #pragma unroll
        for (int ks = 0; ks < 4; ks++) {
            unsigned af[4][4], bf[4][2];
            #pragma unroll
            for (int mi = 0; mi < 4; mi++)
                ldsm4(af[mi][0], af[mi][1], af[mi][2], af[mi][3],
                      sa + (wm * 64 + mi * 16 + lrow) * GS_LDH + ks * 16 + lcol);
            #pragma unroll
            for (int p = 0; p < 2; p++) {
                unsigned r0, r1, r2, r3;
                ldsm4(r0, r1, r2, r3,
                      sb + (wn * 32 + p * 16 + brow) * GS_LDH + ks * 16 + bcol);
                bf[2*p][0] = r0; bf[2*p][1] = r1;
                bf[2*p+1][0] = r2; bf[2*p+1][1] = r3;
            }
            #pragma unroll
            for (int mi = 0; mi < 4; mi++)
                #pragma unroll
                for (int ni = 0; ni < 4; ni++)
                    mma16(acc[mi][ni], af[mi], bf[ni][0], bf[ni][1]);
        }
    };

    issue(0); issue(1);
    const int KT = K / 64;
    CP_WAIT(1); __syncthreads();
    for (int kt = 0; kt < KT; kt++) {
        issue(kt + 2);
        compute(kt);
        CP_WAIT(1); __syncthreads();
    }

    #pragma unroll
    for (int mi = 0; mi < 4; mi++) {
        int rb = row0 + wm * 64 + mi * 16 + g;
        #pragma unroll
        for (int ni = 0; ni < 4; ni++) {
            int cb = col0 + wn * 32 + ni * 8 + 2 * tg;
            float b0v = bias ? bias[cb]     : 0.f;
            float b1v = bias ? bias[cb + 1] : 0.f;
            float v00 = acc[mi][ni][0] + b0v, v01 = acc[mi][ni][1] + b1v;
            float v10 = acc[mi][ni][2] + b0v, v11 = acc[mi][ni][3] + b1v;
            if (OUT_HALF) {
                __half* C = (__half*)Cv;
                *(__half2*)(C + (size_t)rb * ldc + cb) = __floats2half2_rn(v00, v01);
                *(__half2*)(C + (size_t)(rb + 8) * ldc + cb) = __floats2half2_rn(v10, v11);
            } else {
                float* C = (float*)Cv;
                v00 += resid[(size_t)rb * ldc + cb];
                v01 += resid[(size_t)rb * ldc + cb + 1];
                v10 += resid[(size_t)(rb + 8) * ldc + cb];
                v11 += resid[(size_t)(rb + 8) * ldc + cb + 1];
                *(float2*)(C + (size_t)rb * ldc + cb)       = make_float2(v00, v01);
                *(float2*)(C + (size_t)(rb + 8) * ldc + cb) = make_float2(v10, v11);
            }
        }
    }
}

// ---------------------------------------------------------------------------
// Weight prep
// ---------------------------------------------------------------------------
// out[N][K] = fp16(in[K][N]) transpose
__global__ void wt_round_T(const float* __restrict__ in, __half* __restrict__ out,
                           int K, int N)
{
    __shared__ float t[32][33];
    int n0 = blockIdx.x * 32, k0 = blockIdx.y * 32;
    int tx = threadIdx.x, ty = threadIdx.y;
    #pragma unroll
    for (int i = 0; i < 32; i += 8)
        t[ty + i][tx] = in[(size_t)(k0 + ty + i) * N + n0 + tx];
    __syncthreads();
    #pragma unroll
    for (int i = 0; i < 32; i += 8)
        out[(size_t)(n0 + ty + i) * K + k0 + tx] = __float2half_rn(t[tx][ty + i]);
}

// QKV weight prep with output-row permutation:
//   old col n = h*192 + d*3 + s  ->  new row n' = s*1024 + h*64 + d
__global__ void wqkv_prep(const float* __restrict__ in, __half* __restrict__ out)
{
    __shared__ float t[32][33];
    int n0 = blockIdx.x * 32, k0 = blockIdx.y * 32;
    int tx = threadIdx.x, ty = threadIdx.y;
    #pragma unroll
    for (int i = 0; i < 32; i += 8)
        t[ty + i][tx] = in[(size_t)(k0 + ty + i) * (3 * DIM) + n0 + tx];
    __syncthreads();
    #pragma unroll
    for (int i = 0; i < 32; i += 8) {
        int n = n0 + ty + i;
        int h = n / 192, r = n - h * 192;
        int d = r / 3, s = r - d * 3;
        int np = s * DIM + h * HD + d;
        out[(size_t)np * DIM + k0 + tx] = __float2half_rn(t[tx][ty + i]);
    }
}

__global__ void bqkv_perm(const float* __restrict__ b)
{
    int n = blockIdx.x * 256 + threadIdx.x;
    if (n >= 3 * DIM) return;
    int h = n / 192, r = n - h * 192;
    int d = r / 3, s = r - d * 3;
    g_bqkv[s * DIM + h * HD + d] = b[n];
}

__global__ void round_copy(const float* __restrict__ src, __half* __restrict__ dst,
                           size_t n2)
{
    size_t idx = (size_t)blockIdx.x * blockDim.x + threadIdx.x;
    if (idx >= n2) return;
    float2 v = *(const float2*)(src + idx * 2);
    *(__half2*)(dst + idx * 2) = __floats2half2_rn(v.x, v.y);
}

// copy Wf^T scratch [2048][1024] into w0T[:, 1024:2048]
__global__ void copy_wf()
{
    size_t idx = (size_t)blockIdx.x * blockDim.x + threadIdx.x;   // half2 units
    if (idx >= (size_t)(2 * DIM) * DIM / 2) return;
    size_t n = idx / (DIM / 2);
    size_t d2 = idx % (DIM / 2);
    *(__half2*)(g_w0T + n * (2 * DIM) + DIM + d2 * 2) =
        *(__half2*)(g_wf + n * DIM + d2 * 2);
}

// fused bias: b0f[n] = ffn0_b[n] + sum_e out_b[e] * ffn0_w[(1024+e)*2048 + n]
__global__ void bias_fuse(const float* __restrict__ ffn0_b,
                          const float* __restrict__ out_b,
                          const float* __restrict__ ffn0_w)
{
    int n = blockIdx.x * 256 + threadIdx.x;
    float acc = ffn0_b[n];
    for (int e = 0; e < DIM; e++)
        acc = fmaf(out_b[e], ffn0_w[(size_t)(DIM + e) * (2 * DIM) + n], acc);
    g_b0f[n] = acc;
}

// ---------------------------------------------------------------------------
// RoPE in place on q|k columns of g_qkv (v untouched).
// One thread per (b, n, h, pair): rotates q[2i,2i+1] and k[2i,2i+1].
// ---------------------------------------------------------------------------
__global__ void rope_inplace(const float* __restrict__ enc)
{
    size_t idx = (size_t)blockIdx.x * blockDim.x + threadIdx.x;
    const size_t total = (size_t)MTOK * NH * (HD / 2);
    if (idx >= total) return;
    int i = idx & 31;                 // pair index
    size_t t = idx >> 5;
    int h = (int)(t & (NH - 1));
    size_t tok = t >> 4;              // b*2048 + n
    int n = (int)(tok & (NSEQ - 1));

    const float* e0 = enc + (size_t)n * HD + i * 2;
    const float* e1 = enc + (size_t)NSEQ * HD + (size_t)n * HD + i * 2;
    float f00 = e0[0], f01 = e0[1], f10 = e1[0], f11 = e1[1];

    __half* qp = g_qkv + tok * (3 * DIM) + h * HD + i * 2;
    __half* kp = qp + DIM;

    float2 qv = __half22float2(*(__half2*)qp);
    float2 kv = __half22float2(*(__half2*)kp);
    *(__half2*)qp = __floats2half2_rn(qv.x * f00 - qv.y * f10,
                                      qv.y * f01 + qv.x * f11);
    *(__half2*)kp = __floats2half2_rn(kv.x * f00 - kv.y * f10,
                                      kv.y * f01 + kv.x * f11);
}

// ---------------------------------------------------------------------------
// Flash attention over permuted qkv buffer (row stride 3*DIM).
// fp16 mma m16n8k16, HD=64, cp.async double-buffered K/V; P in registers;
// S/PV in two 64-col KV chunks; 2 CTAs/SM; base-2 softmax.
// smem (halves): Qs [128][72]; 2 x (Ks [128][72] + Vs [128][72]).
// ---------------------------------------------------------------------------
#define FL_KV_OFF   9216
#define FL_SMEM_BYTES (46080 * 2)
#define SC_LOG2E 0.18033688011112042f   // 0.125 * log2(e)
#define QKV_LD (3 * DIM)

__global__ __launch_bounds__(256, 2) void flash_kernel(
    const __half* __restrict__ QKV, __half* __restrict__ O)
{
    extern __shared__ __half sm[];

    const int tid  = threadIdx.x;
    const int w    = tid >> 5, lane = tid & 31;
    const int g    = lane >> 2, tg = lane & 3;
    const int bh   = blockIdx.y;
    const int q0   = blockIdx.x * 128;
    const int b    = bh >> 4, h = bh & 15;

    const int lrow = (lane & 7) + ((lane >> 3) & 1) * 8;
    const int lcol = ((lane >> 4) & 1) * 8;
    const int brow = (lane & 7) + ((lane >> 4) & 1) * 8;
    const int bcol = ((lane >> 3) & 1) * 8;

    const __half* Qp = QKV + ((size_t)b * NSEQ) * QKV_LD + h * HD;
    const __half* Kp = Qp + DIM;
    const __half* Vp = Qp + 2 * DIM;

    auto issue = [&](int j) {
        __half* Kb = sm + FL_KV_OFF + (j & 1) * 18432;
        __half* Vb = Kb + 9216;
        #pragma unroll
        for (int i = 0; i < 4; i++) {
            int id = tid + i * 256;
            int r = id >> 3, c = (id & 7) * 8;
            size_t go = (size_t)(j * 128 + r) * QKV_LD + c;
            cp16(Kb + r * 72 + c, Kp + go);
            cp16(Vb + r * 72 + c, Vp + go);
        }
        CP_COMMIT();
    };

    issue(0);

    #pragma unroll
    for (int i = 0; i < 4; i++) {
        int id = tid + i * 256;
        int r = id >> 3, c = (id & 7) * 8;
        *(uint4*)(sm + r * 72 + c) =
            *(const uint4*)(Qp + (size_t)(q0 + r) * QKV_LD + c);
    }
    __syncthreads();
    unsigned qf[4][4];
    #pragma unroll
    for (int ks = 0; ks < 4; ks++)
        ldsm4(qf[ks][0], qf[ks][1], qf[ks][2], qf[ks][3],
              sm + (w * 16 + lrow) * 72 + ks * 16 + lcol);

    float m0 = -1e30f, m1 = -1e30f, l0 = 0.f, l1 = 0.f;
    float oa[8][4] = {};

    for (int j = 0; j < 16; j++) {
        if (j < 15) { issue(j + 1); CP_WAIT(1); }
        else        { CP_WAIT(0); }
        __syncthreads();

        const __half* Ks = sm + FL_KV_OFF + (j & 1) * 18432;
        const __half* Vs = Ks + 9216;

        #pragma unroll
        for (int half = 0; half < 2; half++) {
            float s[8][4];
            #pragma unroll
            for (int ni = 0; ni < 8; ni++)
                s[ni][0] = s[ni][1] = s[ni][2] = s[ni][3] = 0.f;
            #pragma unroll
            for (int ks = 0; ks < 4; ks++) {
                #pragma unroll
                for (int n2 = 0; n2 < 4; n2++) {
                    unsigned r0, r1, r2, r3;
                    ldsm4(r0, r1, r2, r3,
                          Ks + (half * 64 + n2 * 16 + brow) * 72 + ks * 16 + bcol);
                    mma16(s[2*n2],     qf[ks], r0, r1);
                    mma16(s[2*n2 + 1], qf[ks], r2, r3);
                }
            }

            float mt0 = -1e30f, mt1 = -1e30f;
            #pragma unroll
            for (int ni = 0; ni < 8; ni++) {
                s[ni][0] *= SC_LOG2E; s[ni][1] *= SC_LOG2E;
                s[ni][2] *= SC_LOG2E; s[ni][3] *= SC_LOG2E;
                mt0 = fmaxf(mt0, fmaxf(s[ni][0], s[ni][1]));
                mt1 = fmaxf(mt1, fmaxf(s[ni][2], s[ni][3]));
            }
            mt0 = fmaxf(mt0, __shfl_xor_sync(~0u, mt0, 1));
            mt0 = fmaxf(mt0, __shfl_xor_sync(~0u, mt0, 2));
            mt1 = fmaxf(mt1, __shfl_xor_sync(~0u, mt1, 1));
            mt1 = fmaxf(mt1, __shfl_xor_sync(~0u, mt1, 2));
            float m0n = fmaxf(m0, mt0), m1n = fmaxf(m1, mt1);
            bool changed = (m0n > m0) || (m1n > m1);
            float rs0 = 0.f, rs1 = 0.f;
            #pragma unroll
            for (int ni = 0; ni < 8; ni++) {
                s[ni][0] = exp2f(s[ni][0] - m0n);
                s[ni][1] = exp2f(s[ni][1] - m0n);
                s[ni][2] = exp2f(s[ni][2] - m1n);
                s[ni][3] = exp2f(s[ni][3] - m1n);
                rs0 += s[ni][0] + s[ni][1];
                rs1 += s[ni][2] + s[ni][3];
            }
            rs0 += __shfl_xor_sync(~0u, rs0, 1); rs0 += __shfl_xor_sync(~0u, rs0, 2);
            rs1 += __shfl_xor_sync(~0u, rs1, 1); rs1 += __shfl_xor_sync(~0u, rs1, 2);
            if (__any_sync(~0u, changed)) {
                float c0 = exp2f(m0 - m0n), c1 = exp2f(m1 - m1n);
                l0 = l0 * c0 + rs0; l1 = l1 * c1 + rs1;
                #pragma unroll
                for (int ni = 0; ni < 8; ni++) {
                    oa[ni][0] *= c0; oa[ni][1] *= c0;
                    oa[ni][2] *= c1; oa[ni][3] *= c1;
                }
                m0 = m0n; m1 = m1n;
            } else {
                l0 += rs0; l1 += rs1;
            }

            #pragma unroll
            for (int c = 0; c < 4; c++) {
                unsigned a[4];
                a[0] = h2bits(s[2*c][0],     s[2*c][1]);
                a[1] = h2bits(s[2*c][2],     s[2*c][3]);
                a[2] = h2bits(s[2*c + 1][0], s[2*c + 1][1]);
                a[3] = h2bits(s[2*c + 1][2], s[2*c + 1][3]);
                #pragma unroll
                for (int n2 = 0; n2 < 4; n2++) {
                    unsigned r0, r1, r2, r3;
                    ldsm4t(r0, r1, r2, r3,
                           Vs + (half * 64 + c * 16 + lrow) * 72 + n2 * 16 + lcol);
                    mma16(oa[2*n2],     a, r0, r1);
                    mma16(oa[2*n2 + 1], a, r2, r3);
                }
            }
        }
        __syncthreads();
    }

    float i0 = 1.f / l0, i1 = 1.f / l1;
    int r0 = q0 + w * 16 + g, r1 = r0 + 8;
    __half* Op = O + ((size_t)b * NSEQ) * DIM + h * HD;
    #pragma unroll
    for (int ni = 0; ni < 8; ni++) {
        int cb = ni * 8 + 2 * tg;
        *(__half2*)(Op + (size_t)r0 * DIM + cb) =
            __floats2half2_rn(oa[ni][0] * i0, oa[ni][1] * i0);
        *(__half2*)(Op + (size_t)r1 * DIM + cb) =
            __floats2half2_rn(oa[ni][2] * i1, oa[ni][3] * i1);
    }
}

// LayerNorm (2048) + exact GELU, in place on g_h (half).
__global__ __launch_bounds__(256) void ln_gelu_kernel(const float* __restrict__ scale,
                                                      const float* __restrict__ bias)
{
    const int n = 2 * DIM;
    __half* p = g_h + (size_t)blockIdx.x * n;
    const int tid = threadIdx.x;
    __shared__ float s8a[8], s8b[8];

    float s = 0.f, sq = 0.f;
    for (int i = tid; i < n / 2; i += 256) {
        float2 v = __half22float2(*(__half2*)(p + i * 2));
        s += v.x + v.y;
        sq = fmaf(v.x, v.x, fmaf(v.y, v.y, sq));
    }
    #pragma unroll
    for (int o = 16; o > 0; o >>= 1) {
        s  += __shfl_xor_sync(~0u, s, o);
        sq += __shfl_xor_sync(~0u, sq, o);
    }
    if ((tid & 31) == 0) { s8a[tid >> 5] = s; s8b[tid >> 5] = sq; }
    __syncthreads();
    s = 0.f; sq = 0.f;
    #pragma unroll
    for (int i = 0; i < 8; i++) { s += s8a[i]; sq += s8b[i]; }
    float mu = s / n;
    float var = sq / n - mu * mu;
    float rstd = rsqrtf(var + 1e-5f);

    for (int i = tid; i < n / 2; i += 256) {
        float2 v = __half22float2(*(__half2*)(p + i * 2));
        float a = (v.x - mu) * rstd * scale[i * 2]     + bias[i * 2];
        float c = (v.y - mu) * rstd * scale[i * 2 + 1] + bias[i * 2 + 1];
        a = 0.5f * a * (1.f + erff(a * 0.70710678118654752f));
        c = 0.5f * c * (1.f + erff(c * 0.70710678118654752f));
        *(__half2*)(p + i * 2) = __floats2half2_rn(a, c);
    }
}

// ---------------------------------------------------------------------------
// Host
// ---------------------------------------------------------------------------
static inline void* sym(const void* s)
{
    void* p = nullptr;
    cudaGetSymbolAddress(&p, s);
    return p;
}

extern "C" void kernel_launch(void* const* d_in, const int* in_sizes, int n_in,
                              void* d_out, int out_size)
{
    const float* x       = (const float*)d_in[0];
    const float* enc     = (const float*)d_in[1];
    const float* Wqkv_w  = (const float*)d_in[2];
    const float* Wqkv_b  = (const float*)d_in[3];
    const float* out_w   = (const float*)d_in[4];
    const float* out_b   = (const float*)d_in[5];
    const float* ffn0_w  = (const float*)d_in[6];
    const float* ffn0_b  = (const float*)d_in[7];
    const float* ln_s    = (const float*)d_in[8];
    const float* ln_b    = (const float*)d_in[9];
    const float* ffn3_w  = (const float*)d_in[10];
    const float* ffn3_b  = (const float*)d_in[11];
    float* out = (float*)d_out;

    __half* xr     = (__half*)sym(g_xr);
    __half* qkv    = (__half*)sym(g_qkv);
    __half* msgin  = (__half*)sym(g_msgin);
    __half* hbuf   = (__half*)sym(g_h);
    __half* wqkvT  = (__half*)sym(g_wqkvT);
    float*  bqkv   = (float*)sym(g_bqkv);
    __half* woutNT = (__half*)sym(g_woutNT);
    __half* w0T    = (__half*)sym(g_w0T);
    __half* wf     = (__half*)sym(g_wf);
    __half* w3T    = (__half*)sym(g_w3T);
    float*  b0f    = (float*)sym(g_b0f);

    static cudaStream_t s2 = nullptr;
    static cudaEvent_t evFork = nullptr, evJoin = nullptr;
    static bool attr_done = false;
    if (!attr_done) {
        cudaFuncSetAttribute(flash_kernel,
            cudaFuncAttributeMaxDynamicSharedMemorySize, FL_SMEM_BYTES);
        cudaFuncSetAttribute(hgemm<0>,
            cudaFuncAttributeMaxDynamicSharedMemorySize, GEMM_SMEM);
        cudaFuncSetAttribute(hgemm<1>,
            cudaFuncAttributeMaxDynamicSharedMemorySize, GEMM_SMEM);
        cudaStreamCreateWithFlags(&s2, cudaStreamNonBlocking);
        cudaEventCreateWithFlags(&evFork, cudaEventDisableTiming);
        cudaEventCreateWithFlags(&evJoin, cudaEventDisableTiming);
        attr_done = true;
    }

    // ---- fork: FFN-weight prep on side stream (needed only at FFN0) ----
    cudaEventRecord(evFork, 0);
    cudaStreamWaitEvent(s2, evFork, 0);

    wt_round_T<<<dim3(2 * DIM / 32, 2 * DIM / 32), dim3(32, 8), 0, s2>>>(
        ffn0_w, w0T, 2 * DIM, 2 * DIM);
    wt_round_T<<<dim3(DIM / 32, 2 * DIM / 32), dim3(32, 8), 0, s2>>>(
        ffn3_w, w3T, 2 * DIM, DIM);
    round_copy<<<(DIM * DIM / 2 + 255) / 256, 256, 0, s2>>>(
        out_w, woutNT, (size_t)DIM * DIM / 2);
    hgemm<1><<<dim3(DIM / 128, 2 * DIM / 128), 256, GEMM_SMEM, s2>>>(
        w0T + DIM, nullptr, woutNT, nullptr, nullptr, wf,
        DIM, DIM, 2 * DIM, 0, DIM);
    copy_wf<<<((size_t)(2 * DIM) * DIM / 2 + 255) / 256, 256, 0, s2>>>();
    bias_fuse<<<2 * DIM / 256, 256, 0, s2>>>(ffn0_b, out_b, ffn0_w);

    cudaEventRecord(evJoin, s2);

    // ---- main stream: QKV chain ----
    wqkv_prep<<<dim3(3 * DIM / 32, DIM / 32), dim3(32, 8)>>>(Wqkv_w, wqkvT);
    bqkv_perm<<<(3 * DIM + 255) / 256, 256>>>(Wqkv_b);
    round_copy<<<((size_t)MTOK * DIM / 2 + 255) / 256, 256>>>(x, xr, (size_t)MTOK * DIM / 2);

    // QKV projection directly into split [q|k|v] layout
    hgemm<1><<<dim3(3 * DIM / 128, MTOK / 128), 256, GEMM_SMEM>>>(
        xr, nullptr, wqkvT, bqkv, nullptr, qkv, DIM, DIM, DIM, 0, 3 * DIM);

    // RoPE in place on q|k columns
    {
        size_t total = (size_t)MTOK * NH * (HD / 2);
        rope_inplace<<<(unsigned)((total + 255) / 256), 256>>>(enc);
    }

    // Flash attention -> msgin[b,n,h*hd]
    flash_kernel<<<dim3(NSEQ / 128, BHN), 256, FL_SMEM_BYTES>>>(qkv, msgin);

    // ---- join before FFN0 (uses w0T/b0f) ----
    cudaStreamWaitEvent(0, evJoin, 0);

    // FFN0 (out-proj folded): h = [xr | ctx] * [W0_top | Wf]^T + b0f
    hgemm<1><<<dim3(2 * DIM / 128, MTOK / 128), 256, GEMM_SMEM>>>(
        xr, msgin, w0T, b0f, nullptr, hbuf, 2 * DIM, DIM, DIM, DIM, 2 * DIM);

    ln_gelu_kernel<<<MTOK, 256>>>(ln_s, ln_b);

    // FFN3 + residual fused: out = hbuf*W3 + b3 + x
    hgemm<0><<<dim3(DIM / 128, MTOK / 128), 256, GEMM_SMEM>>>(
        hbuf, nullptr, w3T, ffn3_b, x, out, 2 * DIM, 2 * DIM, 2 * DIM, 0, DIM);
}